// round 1
// baseline (speedup 1.0000x reference)
#include <cuda_runtime.h>
#include <math.h>
#include <stdint.h>

#define Bq   2
#define Sq   2048
#define Cc   1536
#define HQn  16
#define HKVn 4
#define DQK  128
#define DV   96
#define EPSf 1e-5f
#define CLIPf 5.0f

// ---------------- scratch (static device allocations; no runtime alloc) ------
__device__ float g_h[Bq*Sq*Cc];          // 6.29M
__device__ float g_q[Bq*Sq*HQn*DQK];     // 8.39M
__device__ float g_k[Bq*Sq*HKVn*DQK];    // 2.10M
__device__ float g_v[Bq*Sq*HKVn*DV];     // 1.57M
__device__ float g_y[Bq*Sq*HQn*DV];      // 6.29M

// ---------------- bn1: h = x * rsqrt(ms+eps) * g -----------------------------
__global__ void bn1_kernel(const float* __restrict__ x, const float* __restrict__ g,
                           const float* __restrict__ ms, float* __restrict__ h, int n)
{
    int i = blockIdx.x * blockDim.x + threadIdx.x;
    if (i < n) {
        int c = i % Cc;
        h[i] = x[i] * rsqrtf(ms[c] + EPSf) * g[c];
    }
}

// ---------------- generic fp32 GEMM: C[M,N] = A[M,K] @ B[K,N] (+bias)(*bn2) --
#define GBM 128
#define GBN 64
#define GBK 16
__global__ void __launch_bounds__(256)
gemm_kernel(const float* __restrict__ A, const float* __restrict__ B,
            float* __restrict__ C, int M, int N, int K,
            const float* __restrict__ bias,
            const float* __restrict__ g2, const float* __restrict__ ms2)
{
    __shared__ float As[GBK][GBM + 1];
    __shared__ float Bs[GBK][GBN];

    int t  = threadIdx.x;
    int tx = t & 15;      // 0..15 -> 4 cols each
    int ty = t >> 4;      // 0..15 -> 8 rows each
    int bm = blockIdx.y * GBM;
    int bn = blockIdx.x * GBN;

    float acc[8][4];
#pragma unroll
    for (int i = 0; i < 8; i++)
#pragma unroll
        for (int j = 0; j < 4; j++) acc[i][j] = 0.f;

    for (int k0 = 0; k0 < K; k0 += GBK) {
        // A tile: 128x16 = 2048 elems, 2 float4 per thread
#pragma unroll
        for (int r = 0; r < 2; r++) {
            int idx = t * 4 + r * 1024;
            int m = idx >> 4, kk = idx & 15;
            float4 av = *reinterpret_cast<const float4*>(A + (size_t)(bm + m) * K + k0 + kk);
            As[kk + 0][m] = av.x; As[kk + 1][m] = av.y;
            As[kk + 2][m] = av.z; As[kk + 3][m] = av.w;
        }
        // B tile: 16x64 = 1024 elems, 1 float4 per thread
        {
            int idx = t * 4;
            int kk = idx >> 6, n = idx & 63;
            float4 bv = *reinterpret_cast<const float4*>(B + (size_t)(k0 + kk) * N + bn + n);
            *reinterpret_cast<float4*>(&Bs[kk][n]) = bv;
        }
        __syncthreads();

#pragma unroll
        for (int kk = 0; kk < GBK; kk++) {
            float a[8], bb[4];
#pragma unroll
            for (int i = 0; i < 8; i++) a[i] = As[kk][ty * 8 + i];
#pragma unroll
            for (int j = 0; j < 4; j++) bb[j] = Bs[kk][tx * 4 + j];
#pragma unroll
            for (int i = 0; i < 8; i++)
#pragma unroll
                for (int j = 0; j < 4; j++) acc[i][j] += a[i] * bb[j];
        }
        __syncthreads();
    }

#pragma unroll
    for (int i = 0; i < 8; i++) {
        int row = bm + ty * 8 + i;
#pragma unroll
        for (int j = 0; j < 4; j++) {
            int col = bn + tx * 4 + j;
            float v = acc[i][j];
            if (bias) v += bias[col];
            if (g2)   v *= g2[col] * rsqrtf(ms2[col] + EPSf);
            C[(size_t)row * N + col] = v;
        }
    }
}

// ---------------- layernorm(128) + RoPE for q/k (in place) -------------------
__global__ void __launch_bounds__(128)
ln_rope_kernel(float* __restrict__ qk, const float* __restrict__ g,
               const float* __restrict__ b, int H)
{
    int row = blockIdx.x;            // over B*S*H
    int tid = threadIdx.x;           // 0..127 = channel
    int s   = (row / H) % Sq;        // sequence position

    float* p = qk + (size_t)row * DQK;
    float v = p[tid];

    __shared__ float red[4], red2[4];
    float sum = v;
#pragma unroll
    for (int o = 16; o > 0; o >>= 1) sum += __shfl_xor_sync(0xffffffffu, sum, o);
    if ((tid & 31) == 0) red[tid >> 5] = sum;
    __syncthreads();
    float mu = (red[0] + red[1] + red[2] + red[3]) * (1.0f / DQK);

    float d = v - mu;
    float sq = d * d;
#pragma unroll
    for (int o = 16; o > 0; o >>= 1) sq += __shfl_xor_sync(0xffffffffu, sq, o);
    if ((tid & 31) == 0) red2[tid >> 5] = sq;
    __syncthreads();
    float var = (red2[0] + red2[1] + red2[2] + red2[3]) * (1.0f / DQK);

    float norm = d * rsqrtf(var + EPSf) * g[tid] + b[tid];

    // RoPE: nf = 64, end = MAX_POS - nf + 1 = 1985
    int f = tid >> 1;
    float geom = expf(logf(1985.0f) * (float)f * (1.0f / 63.0f));
    float invf = 1.0f / ((float)f + geom);
    float th = (float)s * invf;
    float cs = cosf(th), sn = sinf(th);
    float partner = __shfl_xor_sync(0xffffffffu, norm, 1);
    float rot = (tid & 1) ? partner : -partner;
    p[tid] = norm * cs + rot * sn;
}

// ---------------- layernorm(96) for v (in place) -----------------------------
__global__ void __launch_bounds__(96)
ln_v_kernel(float* __restrict__ vv, const float* __restrict__ g, const float* __restrict__ b)
{
    int row = blockIdx.x;            // over B*S*HKV
    int tid = threadIdx.x;           // 0..95
    float* p = vv + (size_t)row * DV;
    float v = p[tid];

    __shared__ float red[3], red2[3];
    float sum = v;
#pragma unroll
    for (int o = 16; o > 0; o >>= 1) sum += __shfl_xor_sync(0xffffffffu, sum, o);
    if ((tid & 31) == 0) red[tid >> 5] = sum;
    __syncthreads();
    float mu = (red[0] + red[1] + red[2]) * (1.0f / DV);

    float d = v - mu;
    float sq = d * d;
#pragma unroll
    for (int o = 16; o > 0; o >>= 1) sq += __shfl_xor_sync(0xffffffffu, sq, o);
    if ((tid & 31) == 0) red2[tid >> 5] = sq;
    __syncthreads();
    float var = (red2[0] + red2[1] + red2[2]) * (1.0f / DV);

    p[tid] = d * rsqrtf(var + EPSf) * g[tid] + b[tid];
}

// ---------------- flash-style attention with tanh soft-cap -------------------
// Grid: (S/128, HQ, B). 128 threads: thread = one query row.
// Soft-cap bounds logits to [-5,5] -> constant softmax shift of CLIP (exact).
#define AK 32   // keys per tile
// smem floats: q 128*129 + k 32*128 + v 32*96 + p 128*33 = 27904 -> 111616 B
#define ATT_SMEM_BYTES (( (128*129) + (AK*DQK) + (AK*DV) + (128*33) ) * 4)

__global__ void __launch_bounds__(128)
attn_kernel(const float* __restrict__ Q, const float* __restrict__ K,
            const float* __restrict__ V, float* __restrict__ Y)
{
    extern __shared__ float sm[];
    float* q_s = sm;                        // [128][129]
    float* k_s = q_s + 128 * 129;           // [32][128]
    float* v_s = k_s + AK * DQK;            // [32][96]
    float* p_s = v_s + AK * DV;             // [128][33]

    int tid = threadIdx.x;
    int qt  = blockIdx.x;
    int h   = blockIdx.y;
    int b   = blockIdx.z;
    int kvh = h & (HKVn - 1);               // h % HKV (torch tile-repeat)
    int q0  = qt * 128;

    // load q tile (128 queries x 128 dims) into padded smem
    const float* Qb = Q + (((size_t)(b * Sq + q0)) * HQn + h) * DQK;
    for (int idx = tid; idx < 128 * 128; idx += 128) {
        int i = idx >> 7, d = idx & 127;
        q_s[i * 129 + d] = Qb[(size_t)i * HQn * DQK + d];
    }

    float acc[DV];
#pragma unroll
    for (int d = 0; d < DV; d++) acc[d] = 0.f;
    float l = 0.f;
    const float scale = 0.08838834764831845f;   // 1/sqrt(128)

    for (int kt = 0; kt < Sq; kt += AK) {
        __syncthreads();   // protect k_s/v_s from previous iteration's readers
        const float* Kb = K + (((size_t)(b * Sq + kt)) * HKVn + kvh) * DQK;
        for (int idx = tid; idx < AK * DQK; idx += 128) {
            int j = idx >> 7, d = idx & 127;
            k_s[idx] = Kb[(size_t)j * HKVn * DQK + d];
        }
        const float* Vb = V + (((size_t)(b * Sq + kt)) * HKVn + kvh) * DV;
        for (int idx = tid; idx < AK * DV; idx += 128) {
            int j = idx / DV, d = idx - j * DV;
            v_s[idx] = Vb[(size_t)j * HKVn * DV + d];
        }
        __syncthreads();

        // logits: lg[j] = q . k_j   (j fully unrolled; d dynamic)
        float lg[AK];
#pragma unroll
        for (int j = 0; j < AK; j++) lg[j] = 0.f;
        const float* qrow = q_s + tid * 129;
        for (int d = 0; d < DQK; d++) {
            float qd = qrow[d];
#pragma unroll
            for (int j = 0; j < AK; j++) lg[j] += qd * k_s[j * DQK + d];
        }

        // soft-cap + exp with constant shift CLIP; stash p in smem (private row)
        float* prow = p_s + tid * 33;
#pragma unroll
        for (int j = 0; j < AK; j++) {
            float tcl = tanhf(lg[j] * (scale / CLIPf)) * CLIPf;
            float pw  = expf(tcl - CLIPf);
            l += pw;
            prow[j] = pw;
        }

        // PV: j dynamic (p from smem), d fully unrolled into register acc
        for (int j = 0; j < AK; j++) {
            float pw = prow[j];
#pragma unroll
            for (int d = 0; d < DV; d++) acc[d] += pw * v_s[j * DV + d];
        }
    }

    float inv = 1.0f / l;
    float* Yrow = Y + (((size_t)(b * Sq + q0 + tid)) * HQn + h) * DV;
#pragma unroll
    for (int d = 0; d < DV; d++) Yrow[d] = acc[d] * inv;
}

// ---------------- host launcher ----------------------------------------------
extern "C" void kernel_launch(void* const* d_in, const int* in_sizes, int n_in,
                              void* d_out, int out_size)
{
    const float* x      = (const float*)d_in[0];
    const float* bn1_g  = (const float*)d_in[1];
    const float* bn1_ms = (const float*)d_in[2];
    const float* Wq     = (const float*)d_in[3];
    const float* Wk     = (const float*)d_in[4];
    const float* Wv     = (const float*)d_in[5];
    const float* qn_g   = (const float*)d_in[6];
    const float* qn_b   = (const float*)d_in[7];
    const float* kn_g   = (const float*)d_in[8];
    const float* kn_b   = (const float*)d_in[9];
    const float* vn_g   = (const float*)d_in[10];
    const float* vn_b   = (const float*)d_in[11];
    const float* Wo     = (const float*)d_in[12];
    const float* bo     = (const float*)d_in[13];
    const float* bn2_g  = (const float*)d_in[14];
    const float* bn2_ms = (const float*)d_in[15];
    float* out = (float*)d_out;

    static float *ph = nullptr, *pq = nullptr, *pk = nullptr, *pv = nullptr, *py = nullptr;
    if (!ph) {
        cudaGetSymbolAddress((void**)&ph, g_h);
        cudaGetSymbolAddress((void**)&pq, g_q);
        cudaGetSymbolAddress((void**)&pk, g_k);
        cudaGetSymbolAddress((void**)&pv, g_v);
        cudaGetSymbolAddress((void**)&py, g_y);
        cudaFuncSetAttribute(attn_kernel, cudaFuncAttributeMaxDynamicSharedMemorySize,
                             ATT_SMEM_BYTES);
    }

    const int M = Bq * Sq;  // 4096

    // 1. pre-scale (rms_bn1)
    {
        int n = M * Cc;
        bn1_kernel<<<(n + 255) / 256, 256>>>(x, bn1_g, bn1_ms, ph, n);
    }
    // 2. projections
    gemm_kernel<<<dim3((HQn * DQK) / GBN, M / GBM), 256>>>(ph, Wq, pq, M, HQn * DQK, Cc,
                                                           nullptr, nullptr, nullptr);
    gemm_kernel<<<dim3((HKVn * DQK) / GBN, M / GBM), 256>>>(ph, Wk, pk, M, HKVn * DQK, Cc,
                                                            nullptr, nullptr, nullptr);
    gemm_kernel<<<dim3((HKVn * DV) / GBN, M / GBM), 256>>>(ph, Wv, pv, M, HKVn * DV, Cc,
                                                           nullptr, nullptr, nullptr);
    // 3. per-head layernorm + rope
    ln_rope_kernel<<<M * HQn, 128>>>(pq, qn_g, qn_b, HQn);
    ln_rope_kernel<<<M * HKVn, 128>>>(pk, kn_g, kn_b, HKVn);
    ln_v_kernel<<<M * HKVn, 96>>>(pv, vn_g, vn_b);
    // 4. attention
    attn_kernel<<<dim3(Sq / 128, HQn, Bq), 128, ATT_SMEM_BYTES>>>(pq, pk, pv, py);
    // 5. output projection (+bias, +rms_bn2) straight into d_out
    gemm_kernel<<<dim3(Cc / GBN, M / GBM), 256>>>(py, Wo, out, M, Cc, Cc,
                                                  bo, bn2_g, bn2_ms);
}

// round 6
// speedup vs baseline: 1.9481x; 1.9481x over previous
#include <cuda_runtime.h>
#include <cuda_bf16.h>
#include <math.h>
#include <stdint.h>

#define Bq   2
#define Sq   2048
#define Cc   1536
#define HQn  16
#define HKVn 4
#define DQK  128
#define DV   96
#define EPSf 1e-5f
#define CLIPf 5.0f

// ---------------- scratch (static device allocations; no runtime alloc) ------
__device__ float g_h[Bq*Sq*Cc];
__device__ float g_q[Bq*Sq*HQn*DQK];
__device__ float g_k[Bq*Sq*HKVn*DQK];
__device__ float g_v[Bq*Sq*HKVn*DV];
__device__ float g_y[Bq*Sq*HQn*DV];

// ---------------- helpers -----------------------------------------------------
__device__ __forceinline__ uint32_t smem_u32(const void* p) {
    uint32_t a;
    asm("{ .reg .u64 t; cvta.to.shared.u64 t, %1; cvt.u32.u64 %0, t; }" : "=r"(a) : "l"(p));
    return a;
}
__device__ __forceinline__ void ldsm_x4(uint32_t* r, uint32_t addr) {
    asm volatile("ldmatrix.sync.aligned.m8n8.x4.shared.b16 {%0,%1,%2,%3}, [%4];"
                 : "=r"(r[0]), "=r"(r[1]), "=r"(r[2]), "=r"(r[3]) : "r"(addr));
}
__device__ __forceinline__ void ldsm_x4t(uint32_t* r, uint32_t addr) {
    asm volatile("ldmatrix.sync.aligned.m8n8.x4.trans.shared.b16 {%0,%1,%2,%3}, [%4];"
                 : "=r"(r[0]), "=r"(r[1]), "=r"(r[2]), "=r"(r[3]) : "r"(addr));
}
__device__ __forceinline__ void mma16816(float* c, const uint32_t* a, const uint32_t* b) {
    asm volatile(
        "mma.sync.aligned.m16n8k16.row.col.f32.bf16.bf16.f32 "
        "{%0,%1,%2,%3}, {%4,%5,%6,%7}, {%8,%9}, {%0,%1,%2,%3};"
        : "+f"(c[0]), "+f"(c[1]), "+f"(c[2]), "+f"(c[3])
        : "r"(a[0]), "r"(a[1]), "r"(a[2]), "r"(a[3]), "r"(b[0]), "r"(b[1]));
}

// ---------------- bn1 ---------------------------------------------------------
__global__ void bn1_kernel(const float* __restrict__ x, const float* __restrict__ g,
                           const float* __restrict__ ms, float* __restrict__ h, int n)
{
    int i = blockIdx.x * blockDim.x + threadIdx.x;
    if (i < n) {
        int c = i % Cc;
        h[i] = x[i] * rsqrtf(ms[c] + EPSf) * g[c];
    }
}

// ================= warp-MMA split-bf16 GEMM ===================================
// C[M,N] = A[M,K] @ B[K,N] fp32. CTA 128x128, 8 warps (2x4) of 64x32 tiles.
// K chunked by 32. A=Ah+Al, B=Bh+Bl; acc += AhBh + AhBl + AlBh (HMMA bf16).
#define APITCH 80      // 32 bf16 = 64B data + 16B pad (bank-tiling, 16B aligned)
#define BPITCH 272     // 128 bf16 = 256B data + 16B pad

__global__ void __launch_bounds__(256, 2)
gemm_mma(const float* __restrict__ A, const float* __restrict__ B,
         float* __restrict__ C, int M, int N, int K,
         const float* __restrict__ bias,
         const float* __restrict__ g2, const float* __restrict__ ms2)
{
    __shared__ __align__(16) uint8_t As_h[128 * APITCH];
    __shared__ __align__(16) uint8_t As_l[128 * APITCH];
    __shared__ __align__(16) uint8_t Bs_h[32 * BPITCH];
    __shared__ __align__(16) uint8_t Bs_l[32 * BPITCH];
    __shared__ float s_bias[128], s_scale[128];

    int t    = threadIdx.x;
    int wid  = t >> 5;
    int lane = t & 31;
    int bm   = blockIdx.y * 128;
    int bn   = blockIdx.x * 128;
    int wm   = (wid & 1) * 64;       // warp M offset in tile
    int wn   = (wid >> 1) * 32;      // warp N offset in tile

    if (t < 128) {
        s_bias[t]  = bias ? bias[bn + t] : 0.f;
        s_scale[t] = g2 ? (g2[bn + t] * rsqrtf(ms2[bn + t] + EPSf)) : 1.f;
    }

    float acc[4][4][4];
#pragma unroll
    for (int i = 0; i < 4; i++)
#pragma unroll
        for (int j = 0; j < 4; j++)
#pragma unroll
            for (int r = 0; r < 4; r++) acc[i][j][r] = 0.f;

    uint32_t ah_base = smem_u32(As_h), al_base = smem_u32(As_l);
    uint32_t bh_base = smem_u32(Bs_h), bl_base = smem_u32(Bs_l);

    // ldmatrix per-lane offsets: group g = lane>>3, row r = lane&7
    int g = lane >> 3, r = lane & 7;
    uint32_t a_off = (uint32_t)(((g & 1) * 8 + r) * APITCH + (g >> 1) * 16);
    uint32_t b_off = (uint32_t)(((g & 1) * 8 + r) * BPITCH + (g >> 1) * 16);

    const int NC = K / 32;
    for (int ic = 0; ic < NC; ic++) {
        int kc = ic * 32;
        __syncthreads();

        // ---- fill A: 128 rows x 32 k (fp32 -> bf16 hi/lo) --------------------
        const float* Ag = A + (size_t)bm * K + kc;
#pragma unroll
        for (int it = 0; it < 4; it++) {
            int idx = t + it * 256;          // 1024 float4
            int m = idx >> 3, kq = idx & 7;  // kq*4 = k element
            float4 a = *reinterpret_cast<const float4*>(Ag + (size_t)m * K + kq * 4);
            __nv_bfloat162 h01 = __nv_bfloat162(__float2bfloat16(a.x), __float2bfloat16(a.y));
            __nv_bfloat162 h23 = __nv_bfloat162(__float2bfloat16(a.z), __float2bfloat16(a.w));
            __nv_bfloat162 l01 = __nv_bfloat162(
                __float2bfloat16(a.x - __bfloat162float(h01.x)),
                __float2bfloat16(a.y - __bfloat162float(h01.y)));
            __nv_bfloat162 l23 = __nv_bfloat162(
                __float2bfloat16(a.z - __bfloat162float(h23.x)),
                __float2bfloat16(a.w - __bfloat162float(h23.y)));
            uint32_t off = (uint32_t)(m * APITCH + kq * 8);
            *reinterpret_cast<uint2*>(As_h + off) = *reinterpret_cast<uint2*>(&h01); // h01,h23 adj
            reinterpret_cast<__nv_bfloat162*>(As_h + off)[0] = h01;
            reinterpret_cast<__nv_bfloat162*>(As_h + off)[1] = h23;
            reinterpret_cast<__nv_bfloat162*>(As_l + off)[0] = l01;
            reinterpret_cast<__nv_bfloat162*>(As_l + off)[1] = l23;
        }
        // ---- fill B: 32 k-rows x 128 n ---------------------------------------
        const float* Bg = B + (size_t)kc * N + bn;
#pragma unroll
        for (int it = 0; it < 4; it++) {
            int idx = t + it * 256;          // 1024 float4
            int k = idx >> 5, nq = idx & 31; // nq*4 = n element
            float4 b = *reinterpret_cast<const float4*>(Bg + (size_t)k * N + nq * 4);
            __nv_bfloat162 h01 = __nv_bfloat162(__float2bfloat16(b.x), __float2bfloat16(b.y));
            __nv_bfloat162 h23 = __nv_bfloat162(__float2bfloat16(b.z), __float2bfloat16(b.w));
            __nv_bfloat162 l01 = __nv_bfloat162(
                __float2bfloat16(b.x - __bfloat162float(h01.x)),
                __float2bfloat16(b.y - __bfloat162float(h01.y)));
            __nv_bfloat162 l23 = __nv_bfloat162(
                __float2bfloat16(b.z - __bfloat162float(h23.x)),
                __float2bfloat16(b.w - __bfloat162float(h23.y)));
            uint32_t off = (uint32_t)(k * BPITCH + nq * 8);
            reinterpret_cast<__nv_bfloat162*>(Bs_h + off)[0] = h01;
            reinterpret_cast<__nv_bfloat162*>(Bs_h + off)[1] = h23;
            reinterpret_cast<__nv_bfloat162*>(Bs_l + off)[0] = l01;
            reinterpret_cast<__nv_bfloat162*>(Bs_l + off)[1] = l23;
        }
        __syncthreads();

        // ---- compute: 2 k16-steps ------------------------------------------
#pragma unroll
        for (int ks = 0; ks < 2; ks++) {
            uint32_t Bh[8], Bl[8];   // [nt*2 + half]
            uint32_t bko = (uint32_t)(ks * 16 * BPITCH) + (uint32_t)(wn * 2);
            ldsm_x4t(&Bh[0], bh_base + b_off + bko);
            ldsm_x4t(&Bh[4], bh_base + b_off + bko + 32);
            ldsm_x4t(&Bl[0], bl_base + b_off + bko);
            ldsm_x4t(&Bl[4], bl_base + b_off + bko + 32);
#pragma unroll
            for (int mt = 0; mt < 4; mt++) {
                uint32_t Ah[4], Al[4];
                uint32_t aro = (uint32_t)((wm + mt * 16) * APITCH + ks * 32);
                ldsm_x4(Ah, ah_base + a_off + aro);
                ldsm_x4(Al, al_base + a_off + aro);
#pragma unroll
                for (int nt = 0; nt < 4; nt++) {
                    mma16816(acc[mt][nt], Ah, &Bh[nt * 2]);
                    mma16816(acc[mt][nt], Ah, &Bl[nt * 2]);
                    mma16816(acc[mt][nt], Al, &Bh[nt * 2]);
                }
            }
        }
    }
    __syncthreads();

    // ---- epilogue: +bias, *scale, store -------------------------------------
#pragma unroll
    for (int mt = 0; mt < 4; mt++) {
#pragma unroll
        for (int nt = 0; nt < 4; nt++) {
            int lcol = wn + nt * 8 + (lane & 3) * 2;
            int row0 = bm + wm + mt * 16 + (lane >> 2);
            float b0 = s_bias[lcol], b1 = s_bias[lcol + 1];
            float s0 = s_scale[lcol], s1 = s_scale[lcol + 1];
            float2 o0, o1;
            o0.x = (acc[mt][nt][0] + b0) * s0;
            o0.y = (acc[mt][nt][1] + b1) * s1;
            o1.x = (acc[mt][nt][2] + b0) * s0;
            o1.y = (acc[mt][nt][3] + b1) * s1;
            *reinterpret_cast<float2*>(C + (size_t)row0 * N + bn + lcol) = o0;
            *reinterpret_cast<float2*>(C + (size_t)(row0 + 8) * N + bn + lcol) = o1;
        }
    }
}

// ---------------- layernorm(128) + RoPE for q/k (in place) -------------------
__global__ void __launch_bounds__(128)
ln_rope_kernel(float* __restrict__ qk, const float* __restrict__ g,
               const float* __restrict__ b, int H)
{
    int row = blockIdx.x;
    int tid = threadIdx.x;
    int s   = (row / H) % Sq;

    float* p = qk + (size_t)row * DQK;
    float v = p[tid];

    __shared__ float red[4], red2[4];
    float sum = v;
#pragma unroll
    for (int o = 16; o > 0; o >>= 1) sum += __shfl_xor_sync(0xffffffffu, sum, o);
    if ((tid & 31) == 0) red[tid >> 5] = sum;
    __syncthreads();
    float mu = (red[0] + red[1] + red[2] + red[3]) * (1.0f / DQK);

    float d = v - mu;
    float sq = d * d;
#pragma unroll
    for (int o = 16; o > 0; o >>= 1) sq += __shfl_xor_sync(0xffffffffu, sq, o);
    if ((tid & 31) == 0) red2[tid >> 5] = sq;
    __syncthreads();
    float var = (red2[0] + red2[1] + red2[2] + red2[3]) * (1.0f / DQK);

    float norm = d * rsqrtf(var + EPSf) * g[tid] + b[tid];

    int f = tid >> 1;
    float geom = expf(logf(1985.0f) * (float)f * (1.0f / 63.0f));
    float invf = 1.0f / ((float)f + geom);
    float th = (float)s * invf;
    float cs = cosf(th), sn = sinf(th);
    float partner = __shfl_xor_sync(0xffffffffu, norm, 1);
    float rot = (tid & 1) ? partner : -partner;
    p[tid] = norm * cs + rot * sn;
}

// ---------------- layernorm(96) for v (in place) -----------------------------
__global__ void __launch_bounds__(96)
ln_v_kernel(float* __restrict__ vv, const float* __restrict__ g, const float* __restrict__ b)
{
    int row = blockIdx.x;
    int tid = threadIdx.x;
    float* p = vv + (size_t)row * DV;
    float v = p[tid];

    __shared__ float red[3], red2[3];
    float sum = v;
#pragma unroll
    for (int o = 16; o > 0; o >>= 1) sum += __shfl_xor_sync(0xffffffffu, sum, o);
    if ((tid & 31) == 0) red[tid >> 5] = sum;
    __syncthreads();
    float mu = (red[0] + red[1] + red[2]) * (1.0f / DV);

    float d = v - mu;
    float sq = d * d;
#pragma unroll
    for (int o = 16; o > 0; o >>= 1) sq += __shfl_xor_sync(0xffffffffu, sq, o);
    if ((tid & 31) == 0) red2[tid >> 5] = sq;
    __syncthreads();
    float var = (red2[0] + red2[1] + red2[2]) * (1.0f / DV);

    p[tid] = d * rsqrtf(var + EPSf) * g[tid] + b[tid];
}

// ---------------- flash-style attention with tanh soft-cap (fp32) ------------
#define AK 32
#define ATT_SMEM_BYTES (( (128*129) + (AK*DQK) + (AK*DV) + (128*33) ) * 4)

__global__ void __launch_bounds__(128)
attn_kernel(const float* __restrict__ Q, const float* __restrict__ K,
            const float* __restrict__ V, float* __restrict__ Y)
{
    extern __shared__ float smf[];
    float* q_s = smf;
    float* k_s = q_s + 128 * 129;
    float* v_s = k_s + AK * DQK;
    float* p_s = v_s + AK * DV;

    int tid = threadIdx.x;
    int qt  = blockIdx.x;
    int h   = blockIdx.y;
    int b   = blockIdx.z;
    int kvh = h & (HKVn - 1);
    int q0  = qt * 128;

    const float* Qb = Q + (((size_t)(b * Sq + q0)) * HQn + h) * DQK;
    for (int idx = tid; idx < 128 * 128; idx += 128) {
        int i = idx >> 7, d = idx & 127;
        q_s[i * 129 + d] = Qb[(size_t)i * HQn * DQK + d];
    }

    float acc[DV];
#pragma unroll
    for (int d = 0; d < DV; d++) acc[d] = 0.f;
    float l = 0.f;
    const float scale = 0.08838834764831845f;

    for (int kt = 0; kt < Sq; kt += AK) {
        __syncthreads();
        const float* Kb = K + (((size_t)(b * Sq + kt)) * HKVn + kvh) * DQK;
        for (int idx = tid; idx < AK * DQK; idx += 128) {
            int j = idx >> 7, d = idx & 127;
            k_s[idx] = Kb[(size_t)j * HKVn * DQK + d];
        }
        const float* Vb = V + (((size_t)(b * Sq + kt)) * HKVn + kvh) * DV;
        for (int idx = tid; idx < AK * DV; idx += 128) {
            int j = idx / DV, d = idx - j * DV;
            v_s[idx] = Vb[(size_t)j * HKVn * DV + d];
        }
        __syncthreads();

        float lg[AK];
#pragma unroll
        for (int j = 0; j < AK; j++) lg[j] = 0.f;
        const float* qrow = q_s + tid * 129;
        for (int d = 0; d < DQK; d++) {
            float qd = qrow[d];
#pragma unroll
            for (int j = 0; j < AK; j++) lg[j] += qd * k_s[j * DQK + d];
        }

        float* prow = p_s + tid * 33;
#pragma unroll
        for (int j = 0; j < AK; j++) {
            float tcl = tanhf(lg[j] * (scale / CLIPf)) * CLIPf;
            float pw  = expf(tcl - CLIPf);
            l += pw;
            prow[j] = pw;
        }

        for (int j = 0; j < AK; j++) {
            float pw = prow[j];
#pragma unroll
            for (int d = 0; d < DV; d++) acc[d] += pw * v_s[j * DV + d];
        }
    }

    float inv = 1.0f / l;
    float* Yrow = Y + (((size_t)(b * Sq + q0 + tid)) * HQn + h) * DV;
#pragma unroll
    for (int d = 0; d < DV; d++) Yrow[d] = acc[d] * inv;
}

// ---------------- host launcher ----------------------------------------------
extern "C" void kernel_launch(void* const* d_in, const int* in_sizes, int n_in,
                              void* d_out, int out_size)
{
    const float* x      = (const float*)d_in[0];
    const float* bn1_g  = (const float*)d_in[1];
    const float* bn1_ms = (const float*)d_in[2];
    const float* Wq     = (const float*)d_in[3];
    const float* Wk     = (const float*)d_in[4];
    const float* Wv     = (const float*)d_in[5];
    const float* qn_g   = (const float*)d_in[6];
    const float* qn_b   = (const float*)d_in[7];
    const float* kn_g   = (const float*)d_in[8];
    const float* kn_b   = (const float*)d_in[9];
    const float* vn_g   = (const float*)d_in[10];
    const float* vn_b   = (const float*)d_in[11];
    const float* Wo     = (const float*)d_in[12];
    const float* bo     = (const float*)d_in[13];
    const float* bn2_g  = (const float*)d_in[14];
    const float* bn2_ms = (const float*)d_in[15];
    float* out = (float*)d_out;

    static float *ph = nullptr, *pq = nullptr, *pk = nullptr, *pv = nullptr, *py = nullptr;
    if (!ph) {
        cudaGetSymbolAddress((void**)&ph, g_h);
        cudaGetSymbolAddress((void**)&pq, g_q);
        cudaGetSymbolAddress((void**)&pk, g_k);
        cudaGetSymbolAddress((void**)&pv, g_v);
        cudaGetSymbolAddress((void**)&py, g_y);
        cudaFuncSetAttribute(attn_kernel, cudaFuncAttributeMaxDynamicSharedMemorySize,
                             ATT_SMEM_BYTES);
    }

    const int M = Bq * Sq;  // 4096

    {
        int n = M * Cc;
        bn1_kernel<<<(n + 255) / 256, 256>>>(x, bn1_g, bn1_ms, ph, n);
    }
    gemm_mma<<<dim3((HQn * DQK) / 128, M / 128), 256>>>(
        ph, Wq, pq, M, HQn * DQK, Cc, nullptr, nullptr, nullptr);
    gemm_mma<<<dim3((HKVn * DQK) / 128, M / 128), 256>>>(
        ph, Wk, pk, M, HKVn * DQK, Cc, nullptr, nullptr, nullptr);
    gemm_mma<<<dim3((HKVn * DV) / 128, M / 128), 256>>>(
        ph, Wv, pv, M, HKVn * DV, Cc, nullptr, nullptr, nullptr);

    ln_rope_kernel<<<M * HQn, 128>>>(pq, qn_g, qn_b, HQn);
    ln_rope_kernel<<<M * HKVn, 128>>>(pk, kn_g, kn_b, HKVn);
    ln_v_kernel<<<M * HKVn, 96>>>(pv, vn_g, vn_b);

    attn_kernel<<<dim3(Sq / 128, HQn, Bq), 128, ATT_SMEM_BYTES>>>(pq, pk, pv, py);

    gemm_mma<<<dim3(Cc / 128, M / 128), 256>>>(
        py, Wo, out, M, Cc, Cc, bo, bn2_g, bn2_ms);
}

// round 12
// speedup vs baseline: 5.9999x; 3.0799x over previous
#include <cuda_runtime.h>
#include <cuda_bf16.h>
#include <math.h>
#include <stdint.h>

#define Bq   2
#define Sq   2048
#define Cc   1536
#define HQn  16
#define HKVn 4
#define DQK  128
#define DV   96
#define EPSf 1e-5f
#define CLIPf 5.0f

// ---------------- scratch (static device allocations; no runtime alloc) ------
__device__ float g_h[Bq*Sq*Cc];
__device__ float g_q[Bq*Sq*HQn*DQK];
__device__ float g_k[Bq*Sq*HKVn*DQK];
__device__ float g_v[Bq*Sq*HKVn*DV];
__device__ float g_y[Bq*Sq*HQn*DV];
__device__ float g_rope[Sq*64*2];        // [s][f] -> cos, sin

// ---------------- helpers -----------------------------------------------------
__device__ __forceinline__ uint32_t smem_u32(const void* p) {
    uint32_t a;
    asm("{ .reg .u64 t; cvta.to.shared.u64 t, %1; cvt.u32.u64 %0, t; }" : "=r"(a) : "l"(p));
    return a;
}
__device__ __forceinline__ void ldsm_x4(uint32_t* r, uint32_t addr) {
    asm volatile("ldmatrix.sync.aligned.m8n8.x4.shared.b16 {%0,%1,%2,%3}, [%4];"
                 : "=r"(r[0]), "=r"(r[1]), "=r"(r[2]), "=r"(r[3]) : "r"(addr));
}
__device__ __forceinline__ void ldsm_x4t(uint32_t* r, uint32_t addr) {
    asm volatile("ldmatrix.sync.aligned.m8n8.x4.trans.shared.b16 {%0,%1,%2,%3}, [%4];"
                 : "=r"(r[0]), "=r"(r[1]), "=r"(r[2]), "=r"(r[3]) : "r"(addr));
}
__device__ __forceinline__ void mma16816(float* c, const uint32_t* a, const uint32_t* b) {
    asm volatile(
        "mma.sync.aligned.m16n8k16.row.col.f32.bf16.bf16.f32 "
        "{%0,%1,%2,%3}, {%4,%5,%6,%7}, {%8,%9}, {%0,%1,%2,%3};"
        : "+f"(c[0]), "+f"(c[1]), "+f"(c[2]), "+f"(c[3])
        : "r"(a[0]), "r"(a[1]), "r"(a[2]), "r"(a[3]), "r"(b[0]), "r"(b[1]));
}
__device__ __forceinline__ void mma_ab(float* c, const uint32_t* a, uint32_t b0, uint32_t b1) {
    asm volatile(
        "mma.sync.aligned.m16n8k16.row.col.f32.bf16.bf16.f32 "
        "{%0,%1,%2,%3}, {%4,%5,%6,%7}, {%8,%9}, {%0,%1,%2,%3};"
        : "+f"(c[0]), "+f"(c[1]), "+f"(c[2]), "+f"(c[3])
        : "r"(a[0]), "r"(a[1]), "r"(a[2]), "r"(a[3]), "r"(b0), "r"(b1));
}
__device__ __forceinline__ uint32_t pack_bf16(float x, float y) {
    __nv_bfloat162 h = __floats2bfloat162_rn(x, y);
    return *reinterpret_cast<uint32_t*>(&h);
}
__device__ __forceinline__ void cvt_split4(float4 a, uint2& hi, uint2& lo) {
    __nv_bfloat162 h0 = __floats2bfloat162_rn(a.x, a.y);
    __nv_bfloat162 h1 = __floats2bfloat162_rn(a.z, a.w);
    __nv_bfloat162 l0 = __floats2bfloat162_rn(a.x - __bfloat162float(h0.x),
                                              a.y - __bfloat162float(h0.y));
    __nv_bfloat162 l1 = __floats2bfloat162_rn(a.z - __bfloat162float(h1.x),
                                              a.w - __bfloat162float(h1.y));
    hi.x = *reinterpret_cast<uint32_t*>(&h0); hi.y = *reinterpret_cast<uint32_t*>(&h1);
    lo.x = *reinterpret_cast<uint32_t*>(&l0); lo.y = *reinterpret_cast<uint32_t*>(&l1);
}

// FFMA-only exp2 for x in [-120, 0]: bit-assembled scale + deg-4 poly. rel err ~4e-5.
__device__ __forceinline__ float exp2_fast(float x) {
    float t  = x + 12582912.0f;          // 1.5*2^23 : round-to-nearest int
    float fn = t - 12582912.0f;          // rint(x)
    float r  = x - fn;                   // [-0.5, 0.5]
    int   ni = ((__float_as_int(t) & 0x7FFFFF) - 0x400000) << 23;
    float xx = r * 0.6931471805599453f;
    float p  = fmaf(xx, 0.04166666791f, 0.1666666665f);
    p = fmaf(xx, p, 0.5f);
    p = fmaf(xx, p, 1.0f);
    p = fmaf(xx, p, 1.0f);
    return __int_as_float(__float_as_int(p) + ni);
}

// f(z) = exp(5*tanh(z/5) - 5), MUFU-free.
// = exp(-10*v/(1+v)) for z>=0, v=e^{-2z/5};  f(-z) = e^{-10}/f(z).
__device__ __forceinline__ float softcap_w(float z) {
    float v = exp2_fast(fabsf(z) * -0.5770780163555852f);   // e^{-2|z|/5} in (0,1]
    float w = 1.0f + v;                                     // [1,2]
    float r = fmaf(w, -0.5f, 1.4571f);                      // ~1/w
    r = r * fmaf(-w, r, 2.0f);
    r = r * fmaf(-w, r, 2.0f);
    float s = v * r;                                        // v/(1+v) in (0,0.5]
    float E = (z >= 0.0f) ? (-14.426950408889634f * s)
                          : fmaf(14.426950408889634f, s, -14.426950408889634f);
    return exp2_fast(E);                                    // 2^E = e^{5tanh(z/5)-5}
}

// ---------------- bn1 ---------------------------------------------------------
__global__ void bn1_kernel(const float* __restrict__ x, const float* __restrict__ g,
                           const float* __restrict__ ms, float* __restrict__ h, int n)
{
    int i = blockIdx.x * blockDim.x + threadIdx.x;
    if (i < n) {
        int c = i % Cc;
        h[i] = x[i] * rsqrtf(ms[c] + EPSf) * g[c];
    }
}

// ================= warp-MMA split-bf16 GEMM (unchanged, passing) ==============
#define APITCH 80
#define BPITCH 272

__global__ void __launch_bounds__(256, 2)
gemm_mma(const float* __restrict__ A, const float* __restrict__ B,
         float* __restrict__ C, int M, int N, int K,
         const float* __restrict__ bias,
         const float* __restrict__ g2, const float* __restrict__ ms2)
{
    __shared__ __align__(16) uint8_t As_h[128 * APITCH];
    __shared__ __align__(16) uint8_t As_l[128 * APITCH];
    __shared__ __align__(16) uint8_t Bs_h[32 * BPITCH];
    __shared__ __align__(16) uint8_t Bs_l[32 * BPITCH];
    __shared__ float s_bias[128], s_scale[128];

    int t    = threadIdx.x;
    int wid  = t >> 5;
    int lane = t & 31;
    int bm   = blockIdx.y * 128;
    int bn   = blockIdx.x * 128;
    int wm   = (wid & 1) * 64;
    int wn   = (wid >> 1) * 32;

    if (t < 128) {
        s_bias[t]  = bias ? bias[bn + t] : 0.f;
        s_scale[t] = g2 ? (g2[bn + t] * rsqrtf(ms2[bn + t] + EPSf)) : 1.f;
    }

    float acc[4][4][4];
#pragma unroll
    for (int i = 0; i < 4; i++)
#pragma unroll
        for (int j = 0; j < 4; j++)
#pragma unroll
            for (int r = 0; r < 4; r++) acc[i][j][r] = 0.f;

    uint32_t ah_base = smem_u32(As_h), al_base = smem_u32(As_l);
    uint32_t bh_base = smem_u32(Bs_h), bl_base = smem_u32(Bs_l);

    int g = lane >> 3, r = lane & 7;
    uint32_t a_off = (uint32_t)(((g & 1) * 8 + r) * APITCH + (g >> 1) * 16);
    uint32_t b_off = (uint32_t)(((g & 1) * 8 + r) * BPITCH + (g >> 1) * 16);

    const int NC = K / 32;
    for (int ic = 0; ic < NC; ic++) {
        int kc = ic * 32;
        __syncthreads();

        const float* Ag = A + (size_t)bm * K + kc;
#pragma unroll
        for (int it = 0; it < 4; it++) {
            int idx = t + it * 256;
            int m = idx >> 3, kq = idx & 7;
            float4 a = *reinterpret_cast<const float4*>(Ag + (size_t)m * K + kq * 4);
            uint2 hi, lo;
            cvt_split4(a, hi, lo);
            uint32_t off = (uint32_t)(m * APITCH + kq * 8);
            *reinterpret_cast<uint2*>(As_h + off) = hi;
            *reinterpret_cast<uint2*>(As_l + off) = lo;
        }
        const float* Bg = B + (size_t)kc * N + bn;
#pragma unroll
        for (int it = 0; it < 4; it++) {
            int idx = t + it * 256;
            int k = idx >> 5, nq = idx & 31;
            float4 b = *reinterpret_cast<const float4*>(Bg + (size_t)k * N + nq * 4);
            uint2 hi, lo;
            cvt_split4(b, hi, lo);
            uint32_t off = (uint32_t)(k * BPITCH + nq * 8);
            *reinterpret_cast<uint2*>(Bs_h + off) = hi;
            *reinterpret_cast<uint2*>(Bs_l + off) = lo;
        }
        __syncthreads();

#pragma unroll
        for (int ks = 0; ks < 2; ks++) {
            uint32_t Bh[8], Bl[8];
            uint32_t bko = (uint32_t)(ks * 16 * BPITCH) + (uint32_t)(wn * 2);
            ldsm_x4t(&Bh[0], bh_base + b_off + bko);
            ldsm_x4t(&Bh[4], bh_base + b_off + bko + 32);
            ldsm_x4t(&Bl[0], bl_base + b_off + bko);
            ldsm_x4t(&Bl[4], bl_base + b_off + bko + 32);
#pragma unroll
            for (int mt = 0; mt < 4; mt++) {
                uint32_t Ah[4], Al[4];
                uint32_t aro = (uint32_t)((wm + mt * 16) * APITCH + ks * 32);
                ldsm_x4(Ah, ah_base + a_off + aro);
                ldsm_x4(Al, al_base + a_off + aro);
#pragma unroll
                for (int nt = 0; nt < 4; nt++) {
                    mma16816(acc[mt][nt], Ah, &Bh[nt * 2]);
                    mma16816(acc[mt][nt], Ah, &Bl[nt * 2]);
                    mma16816(acc[mt][nt], Al, &Bh[nt * 2]);
                }
            }
        }
    }
    __syncthreads();

#pragma unroll
    for (int mt = 0; mt < 4; mt++) {
#pragma unroll
        for (int nt = 0; nt < 4; nt++) {
            int lcol = wn + nt * 8 + (lane & 3) * 2;
            int row0 = bm + wm + mt * 16 + (lane >> 2);
            float b0 = s_bias[lcol], b1 = s_bias[lcol + 1];
            float s0 = s_scale[lcol], s1 = s_scale[lcol + 1];
            float2 o0, o1;
            o0.x = (acc[mt][nt][0] + b0) * s0;
            o0.y = (acc[mt][nt][1] + b1) * s1;
            o1.x = (acc[mt][nt][2] + b0) * s0;
            o1.y = (acc[mt][nt][3] + b1) * s1;
            *reinterpret_cast<float2*>(C + (size_t)row0 * N + bn + lcol) = o0;
            *reinterpret_cast<float2*>(C + (size_t)(row0 + 8) * N + bn + lcol) = o1;
        }
    }
}

// ---------------- RoPE table --------------------------------------------------
__global__ void rope_tab_kernel(float* __restrict__ tab)
{
    int idx = blockIdx.x * blockDim.x + threadIdx.x;
    if (idx < Sq * 64) {
        int s = idx >> 6, f = idx & 63;
        float geom = expf(logf(1985.0f) * (float)f * (1.0f / 63.0f));
        float th = (float)s / ((float)f + geom);
        tab[idx * 2 + 0] = cosf(th);
        tab[idx * 2 + 1] = sinf(th);
    }
}

// ---------------- layernorm(128) + RoPE for q/k (in place) -------------------
__global__ void __launch_bounds__(128)
ln_rope_kernel(float* __restrict__ qk, const float* __restrict__ g,
               const float* __restrict__ b, const float* __restrict__ tab, int H)
{
    int row = blockIdx.x;
    int tid = threadIdx.x;
    int s   = (row / H) % Sq;

    float* p = qk + (size_t)row * DQK;
    float v = p[tid];

    __shared__ float red[4], red2[4];
    float sum = v;
#pragma unroll
    for (int o = 16; o > 0; o >>= 1) sum += __shfl_xor_sync(0xffffffffu, sum, o);
    if ((tid & 31) == 0) red[tid >> 5] = sum;
    __syncthreads();
    float mu = (red[0] + red[1] + red[2] + red[3]) * (1.0f / DQK);

    float d = v - mu;
    float sq = d * d;
#pragma unroll
    for (int o = 16; o > 0; o >>= 1) sq += __shfl_xor_sync(0xffffffffu, sq, o);
    if ((tid & 31) == 0) red2[tid >> 5] = sq;
    __syncthreads();
    float var = (red2[0] + red2[1] + red2[2] + red2[3]) * (1.0f / DQK);

    float norm = d * rsqrtf(var + EPSf) * g[tid] + b[tid];

    float2 cs2 = *reinterpret_cast<const float2*>(tab + ((size_t)s * 64 + (tid >> 1)) * 2);
    float partner = __shfl_xor_sync(0xffffffffu, norm, 1);
    float rot = (tid & 1) ? partner : -partner;
    p[tid] = norm * cs2.x + rot * cs2.y;
}

// ---------------- layernorm(96) for v (in place) -----------------------------
__global__ void __launch_bounds__(96)
ln_v_kernel(float* __restrict__ vv, const float* __restrict__ g, const float* __restrict__ b)
{
    int row = blockIdx.x;
    int tid = threadIdx.x;
    float* p = vv + (size_t)row * DV;
    float v = p[tid];

    __shared__ float red[3], red2[3];
    float sum = v;
#pragma unroll
    for (int o = 16; o > 0; o >>= 1) sum += __shfl_xor_sync(0xffffffffu, sum, o);
    if ((tid & 31) == 0) red[tid >> 5] = sum;
    __syncthreads();
    float mu = (red[0] + red[1] + red[2]) * (1.0f / DV);

    float d = v - mu;
    float sq = d * d;
#pragma unroll
    for (int o = 16; o > 0; o >>= 1) sq += __shfl_xor_sync(0xffffffffu, sq, o);
    if ((tid & 31) == 0) red2[tid >> 5] = sq;
    __syncthreads();
    float var = (red2[0] + red2[1] + red2[2]) * (1.0f / DV);

    p[tid] = d * rsqrtf(var + EPSf) * g[tid] + b[tid];
}

// ================= tensor-core flash attention ================================
// CTA: 128 q rows, 8 warps (16 q each), k-tiles of 64 keys. split-bf16 QK & PV.
#define KT 64
#define QPITCH 272     // 128 bf16 + 16B pad
#define KPITCH 272
#define VPITCH 208     // 96 bf16 + 16B pad
// smem: Qh[128*272] Ql | Kh[64*272] Kl | Vh[64*208] Vl
#define SM_QH 0
#define SM_QL 34816
#define SM_KH 69632
#define SM_KL (SM_KH + 17408)
#define SM_VH (SM_KL + 17408)
#define SM_VL (SM_VH + 13312)
#define ATT_SMEM (SM_VL + 13312)    // 131072

__global__ void __launch_bounds__(256, 1)
attn_mma(const float* __restrict__ Q, const float* __restrict__ K,
         const float* __restrict__ V, float* __restrict__ Y)
{
    extern __shared__ __align__(16) uint8_t sm[];
    uint8_t* Qh = sm + SM_QH;  uint8_t* Ql = sm + SM_QL;
    uint8_t* Kh = sm + SM_KH;  uint8_t* Kl = sm + SM_KL;
    uint8_t* Vh = sm + SM_VH;  uint8_t* Vl = sm + SM_VL;

    int t = threadIdx.x, wid = t >> 5, lane = t & 31;
    int qt = blockIdx.x, h = blockIdx.y, b = blockIdx.z;
    int kvh = h & (HKVn - 1);
    int q0  = qt * 128;

    // ---- load Q tile (scaled by 1/sqrt(128) BEFORE split), hi/lo bf16 -------
    const float qsc = 0.08838834764831845f;
    const float* Qg = Q + ((size_t)(b * Sq + q0) * HQn + h) * DQK;
#pragma unroll
    for (int it = 0; it < 16; it++) {
        int idx = t + it * 256;              // 4096 float4
        int m = idx >> 5, dq = idx & 31;
        float4 a = *reinterpret_cast<const float4*>(Qg + (size_t)m * (HQn * DQK) + dq * 4);
        a.x *= qsc; a.y *= qsc; a.z *= qsc; a.w *= qsc;
        uint2 hi, lo;
        cvt_split4(a, hi, lo);
        uint32_t off = (uint32_t)(m * QPITCH + dq * 8);
        *reinterpret_cast<uint2*>(Qh + off) = hi;
        *reinterpret_cast<uint2*>(Ql + off) = lo;
    }

    uint32_t qh_b = smem_u32(Qh), ql_b = smem_u32(Ql);
    uint32_t kh_b = smem_u32(Kh), kl_b = smem_u32(Kl);
    uint32_t vh_b = smem_u32(Vh), vl_b = smem_u32(Vl);

    int g = lane >> 3, r = lane & 7;
    uint32_t qk_off = (uint32_t)(((g & 1) * 8 + r) * QPITCH + (g >> 1) * 16);
    uint32_t v_off  = (uint32_t)(((g & 1) * 8 + r) * VPITCH + (g >> 1) * 16);
    uint32_t qrow_off = (uint32_t)(wid * 16 * QPITCH);

    float yacc[12][4];
#pragma unroll
    for (int i = 0; i < 12; i++)
#pragma unroll
        for (int j = 0; j < 4; j++) yacc[i][j] = 0.f;
    float lsum0 = 0.f, lsum1 = 0.f;

    for (int kt0 = 0; kt0 < Sq; kt0 += KT) {
        __syncthreads();
        // ---- load K tile 64x128 -> Kh/Kl ------------------------------------
        const float* Kg = K + ((size_t)(b * Sq + kt0) * HKVn + kvh) * DQK;
#pragma unroll
        for (int it = 0; it < 8; it++) {
            int idx = t + it * 256;          // 2048 float4
            int m = idx >> 5, dq = idx & 31;
            float4 a = *reinterpret_cast<const float4*>(Kg + (size_t)m * (HKVn * DQK) + dq * 4);
            uint2 hi, lo;
            cvt_split4(a, hi, lo);
            uint32_t off = (uint32_t)(m * KPITCH + dq * 8);
            *reinterpret_cast<uint2*>(Kh + off) = hi;
            *reinterpret_cast<uint2*>(Kl + off) = lo;
        }
        // ---- load V tile 64x96 -> Vh/Vl -------------------------------------
        const float* Vg = V + ((size_t)(b * Sq + kt0) * HKVn + kvh) * DV;
#pragma unroll
        for (int it = 0; it < 6; it++) {
            int idx = t + it * 256;          // 1536 float4
            int m = idx / 24, c = idx - m * 24;
            float4 a = *reinterpret_cast<const float4*>(Vg + (size_t)m * (HKVn * DV) + c * 4);
            uint2 hi, lo;
            cvt_split4(a, hi, lo);
            uint32_t off = (uint32_t)(m * VPITCH + c * 8);
            *reinterpret_cast<uint2*>(Vh + off) = hi;
            *reinterpret_cast<uint2*>(Vl + off) = lo;
        }
        __syncthreads();

        // ---- QK: S[8 n-tiles][4] over d=128 ---------------------------------
        float S[8][4];
#pragma unroll
        for (int i = 0; i < 8; i++)
#pragma unroll
            for (int j = 0; j < 4; j++) S[i][j] = 0.f;

#pragma unroll
        for (int kt16 = 0; kt16 < 8; kt16++) {
            uint32_t aQh[4], aQl[4];
            uint32_t qa = qk_off + qrow_off + (uint32_t)(kt16 * 32);
            ldsm_x4(aQh, qh_b + qa);
            ldsm_x4(aQl, ql_b + qa);
#pragma unroll
            for (int nt2 = 0; nt2 < 4; nt2++) {
                uint32_t bKh[4], bKl[4];
                uint32_t ka = qk_off + (uint32_t)(nt2 * 16 * KPITCH + kt16 * 32);
                ldsm_x4(bKh, kh_b + ka);
                ldsm_x4(bKl, kl_b + ka);
                // n-tile 2*nt2: {r0,r2}; 2*nt2+1: {r1,r3}
                mma_ab(S[2*nt2+0], aQh, bKh[0], bKh[2]);
                mma_ab(S[2*nt2+0], aQh, bKl[0], bKl[2]);
                mma_ab(S[2*nt2+0], aQl, bKh[0], bKh[2]);
                mma_ab(S[2*nt2+1], aQh, bKh[1], bKh[3]);
                mma_ab(S[2*nt2+1], aQh, bKl[1], bKl[3]);
                mma_ab(S[2*nt2+1], aQl, bKh[1], bKh[3]);
            }
        }

        // ---- softcap + exp (MUFU-free), accumulate row sums -----------------
#pragma unroll
        for (int nt = 0; nt < 8; nt++) {
            float f0 = softcap_w(S[nt][0]);
            float f1 = softcap_w(S[nt][1]);
            float f2 = softcap_w(S[nt][2]);
            float f3 = softcap_w(S[nt][3]);
            S[nt][0] = f0; S[nt][1] = f1; S[nt][2] = f2; S[nt][3] = f3;
            lsum0 += f0 + f1;
            lsum1 += f2 + f3;
        }

        // ---- PV: Y += P @ V --------------------------------------------------
#pragma unroll
        for (int kt16 = 0; kt16 < 4; kt16++) {
            uint32_t aPh[4], aPl[4];
            {
                float* c0 = S[2*kt16];
                float* c1 = S[2*kt16+1];
                aPh[0] = pack_bf16(c0[0], c0[1]);
                aPh[1] = pack_bf16(c0[2], c0[3]);
                aPh[2] = pack_bf16(c1[0], c1[1]);
                aPh[3] = pack_bf16(c1[2], c1[3]);
                __nv_bfloat162* p0 = reinterpret_cast<__nv_bfloat162*>(&aPh[0]);
                __nv_bfloat162* p1 = reinterpret_cast<__nv_bfloat162*>(&aPh[1]);
                __nv_bfloat162* p2 = reinterpret_cast<__nv_bfloat162*>(&aPh[2]);
                __nv_bfloat162* p3 = reinterpret_cast<__nv_bfloat162*>(&aPh[3]);
                aPl[0] = pack_bf16(c0[0] - __bfloat162float(p0->x), c0[1] - __bfloat162float(p0->y));
                aPl[1] = pack_bf16(c0[2] - __bfloat162float(p1->x), c0[3] - __bfloat162float(p1->y));
                aPl[2] = pack_bf16(c1[0] - __bfloat162float(p2->x), c1[1] - __bfloat162float(p2->y));
                aPl[3] = pack_bf16(c1[2] - __bfloat162float(p3->x), c1[3] - __bfloat162float(p3->y));
            }
#pragma unroll
            for (int nv2 = 0; nv2 < 6; nv2++) {
                uint32_t bVh[4], bVl[4];
                uint32_t va = v_off + (uint32_t)(kt16 * 16 * VPITCH + nv2 * 32);
                ldsm_x4t(bVh, vh_b + va);
                ldsm_x4t(bVl, vl_b + va);
                mma_ab(yacc[2*nv2+0], aPh, bVh[0], bVh[1]);
                mma_ab(yacc[2*nv2+0], aPh, bVl[0], bVl[1]);
                mma_ab(yacc[2*nv2+0], aPl, bVh[0], bVh[1]);
                mma_ab(yacc[2*nv2+1], aPh, bVh[2], bVh[3]);
                mma_ab(yacc[2*nv2+1], aPh, bVl[2], bVl[3]);
                mma_ab(yacc[2*nv2+1], aPl, bVh[2], bVh[3]);
            }
        }
    }

    // ---- normalize + store ---------------------------------------------------
    lsum0 += __shfl_xor_sync(0xffffffffu, lsum0, 1);
    lsum0 += __shfl_xor_sync(0xffffffffu, lsum0, 2);
    lsum1 += __shfl_xor_sync(0xffffffffu, lsum1, 1);
    lsum1 += __shfl_xor_sync(0xffffffffu, lsum1, 2);
    float inv0 = 1.0f / lsum0;
    float inv1 = 1.0f / lsum1;

    int row0 = q0 + wid * 16 + (lane >> 2);
    float* Y0 = Y + ((size_t)(b * Sq + row0) * HQn + h) * DV;
    float* Y1 = Y + ((size_t)(b * Sq + row0 + 8) * HQn + h) * DV;
    int cbase = (lane & 3) * 2;
#pragma unroll
    for (int nt = 0; nt < 12; nt++) {
        float2 o0, o1;
        o0.x = yacc[nt][0] * inv0; o0.y = yacc[nt][1] * inv0;
        o1.x = yacc[nt][2] * inv1; o1.y = yacc[nt][3] * inv1;
        *reinterpret_cast<float2*>(Y0 + nt * 8 + cbase) = o0;
        *reinterpret_cast<float2*>(Y1 + nt * 8 + cbase) = o1;
    }
}

// ---------------- host launcher ----------------------------------------------
extern "C" void kernel_launch(void* const* d_in, const int* in_sizes, int n_in,
                              void* d_out, int out_size)
{
    const float* x      = (const float*)d_in[0];
    const float* bn1_g  = (const float*)d_in[1];
    const float* bn1_ms = (const float*)d_in[2];
    const float* Wq     = (const float*)d_in[3];
    const float* Wk     = (const float*)d_in[4];
    const float* Wv     = (const float*)d_in[5];
    const float* qn_g   = (const float*)d_in[6];
    const float* qn_b   = (const float*)d_in[7];
    const float* kn_g   = (const float*)d_in[8];
    const float* kn_b   = (const float*)d_in[9];
    const float* vn_g   = (const float*)d_in[10];
    const float* vn_b   = (const float*)d_in[11];
    const float* Wo     = (const float*)d_in[12];
    const float* bo     = (const float*)d_in[13];
    const float* bn2_g  = (const float*)d_in[14];
    const float* bn2_ms = (const float*)d_in[15];
    float* out = (float*)d_out;

    static float *ph = nullptr, *pq = nullptr, *pk = nullptr, *pv = nullptr,
                 *py = nullptr, *prope = nullptr;
    if (!ph) {
        cudaGetSymbolAddress((void**)&ph, g_h);
        cudaGetSymbolAddress((void**)&pq, g_q);
        cudaGetSymbolAddress((void**)&pk, g_k);
        cudaGetSymbolAddress((void**)&pv, g_v);
        cudaGetSymbolAddress((void**)&py, g_y);
        cudaGetSymbolAddress((void**)&prope, g_rope);
        cudaFuncSetAttribute(attn_mma, cudaFuncAttributeMaxDynamicSharedMemorySize,
                             ATT_SMEM);
    }

    const int M = Bq * Sq;  // 4096

    {
        int n = M * Cc;
        bn1_kernel<<<(n + 255) / 256, 256>>>(x, bn1_g, bn1_ms, ph, n);
    }
    rope_tab_kernel<<<(Sq * 64 + 255) / 256, 256>>>(prope);

    gemm_mma<<<dim3((HQn * DQK) / 128, M / 128), 256>>>(
        ph, Wq, pq, M, HQn * DQK, Cc, nullptr, nullptr, nullptr);
    gemm_mma<<<dim3((HKVn * DQK) / 128, M / 128), 256>>>(
        ph, Wk, pk, M, HKVn * DQK, Cc, nullptr, nullptr, nullptr);
    gemm_mma<<<dim3((HKVn * DV) / 128, M / 128), 256>>>(
        ph, Wv, pv, M, HKVn * DV, Cc, nullptr, nullptr, nullptr);

    ln_rope_kernel<<<M * HQn, 128>>>(pq, qn_g, qn_b, prope, HQn);
    ln_rope_kernel<<<M * HKVn, 128>>>(pk, kn_g, kn_b, prope, HKVn);
    ln_v_kernel<<<M * HKVn, 96>>>(pv, vn_g, vn_b);

    attn_mma<<<dim3(Sq / 128, HQn, Bq), 256, ATT_SMEM>>>(pq, pk, pv, py);

    gemm_mma<<<dim3(Cc / 128, M / 128), 256>>>(
        py, Wo, out, M, Cc, Cc, bo, bn2_g, bn2_ms);
}

// round 15
// speedup vs baseline: 6.0791x; 1.0132x over previous
#include <cuda_runtime.h>
#include <cuda_bf16.h>
#include <math.h>
#include <stdint.h>

#define Bq   2
#define Sq   2048
#define Cc   1536
#define HQn  16
#define HKVn 4
#define DQK  128
#define DV   96
#define EPSf 1e-5f
#define CLIPf 5.0f

// ---------------- scratch (static device allocations; no runtime alloc) ------
__device__ float g_q[Bq*Sq*HQn*DQK];
__device__ float g_k[Bq*Sq*HKVn*DQK];
__device__ float g_v[Bq*Sq*HKVn*DV];
__device__ float g_y[Bq*Sq*HQn*DV];
__device__ float g_rope[Sq*64*2];        // [s][f] -> cos, sin
__device__ float g_sc[Cc];               // bn1 per-channel scale

// ---------------- helpers -----------------------------------------------------
__device__ __forceinline__ uint32_t smem_u32(const void* p) {
    uint32_t a;
    asm("{ .reg .u64 t; cvta.to.shared.u64 t, %1; cvt.u32.u64 %0, t; }" : "=r"(a) : "l"(p));
    return a;
}
__device__ __forceinline__ void ldsm_x4(uint32_t* r, uint32_t addr) {
    asm volatile("ldmatrix.sync.aligned.m8n8.x4.shared.b16 {%0,%1,%2,%3}, [%4];"
                 : "=r"(r[0]), "=r"(r[1]), "=r"(r[2]), "=r"(r[3]) : "r"(addr));
}
__device__ __forceinline__ void ldsm_x4t(uint32_t* r, uint32_t addr) {
    asm volatile("ldmatrix.sync.aligned.m8n8.x4.trans.shared.b16 {%0,%1,%2,%3}, [%4];"
                 : "=r"(r[0]), "=r"(r[1]), "=r"(r[2]), "=r"(r[3]) : "r"(addr));
}
__device__ __forceinline__ void mma16816(float* c, const uint32_t* a, const uint32_t* b) {
    asm volatile(
        "mma.sync.aligned.m16n8k16.row.col.f32.bf16.bf16.f32 "
        "{%0,%1,%2,%3}, {%4,%5,%6,%7}, {%8,%9}, {%0,%1,%2,%3};"
        : "+f"(c[0]), "+f"(c[1]), "+f"(c[2]), "+f"(c[3])
        : "r"(a[0]), "r"(a[1]), "r"(a[2]), "r"(a[3]), "r"(b[0]), "r"(b[1]));
}
__device__ __forceinline__ void mma_ab(float* c, const uint32_t* a, uint32_t b0, uint32_t b1) {
    asm volatile(
        "mma.sync.aligned.m16n8k16.row.col.f32.bf16.bf16.f32 "
        "{%0,%1,%2,%3}, {%4,%5,%6,%7}, {%8,%9}, {%0,%1,%2,%3};"
        : "+f"(c[0]), "+f"(c[1]), "+f"(c[2]), "+f"(c[3])
        : "r"(a[0]), "r"(a[1]), "r"(a[2]), "r"(a[3]), "r"(b0), "r"(b1));
}
__device__ __forceinline__ uint32_t pack_bf16(float x, float y) {
    __nv_bfloat162 h = __floats2bfloat162_rn(x, y);
    return *reinterpret_cast<uint32_t*>(&h);
}
__device__ __forceinline__ void cvt_split4(float4 a, uint2& hi, uint2& lo) {
    __nv_bfloat162 h0 = __floats2bfloat162_rn(a.x, a.y);
    __nv_bfloat162 h1 = __floats2bfloat162_rn(a.z, a.w);
    __nv_bfloat162 l0 = __floats2bfloat162_rn(a.x - __bfloat162float(h0.x),
                                              a.y - __bfloat162float(h0.y));
    __nv_bfloat162 l1 = __floats2bfloat162_rn(a.z - __bfloat162float(h1.x),
                                              a.w - __bfloat162float(h1.y));
    hi.x = *reinterpret_cast<uint32_t*>(&h0); hi.y = *reinterpret_cast<uint32_t*>(&h1);
    lo.x = *reinterpret_cast<uint32_t*>(&l0); lo.y = *reinterpret_cast<uint32_t*>(&l1);
}

// FFMA-only exp2 for x in [-120, 0]. rel err ~4e-5.
__device__ __forceinline__ float exp2_fast(float x) {
    float t  = x + 12582912.0f;
    int   ni = ((__float_as_int(t) & 0x7FFFFF) - 0x400000) << 23;
    float fn = t - 12582912.0f;
    float r  = x - fn;
    float xx = r * 0.6931471805599453f;
    float p  = fmaf(xx, 0.04166666791f, 0.1666666665f);
    p = fmaf(xx, p, 0.5f);
    p = fmaf(xx, p, 1.0f);
    p = fmaf(xx, p, 1.0f);
    return __int_as_float(__float_as_int(p) + ni);
}

// f(z) = exp(5*tanh(z/5) - 5), MUFU-free.
__device__ __forceinline__ float softcap_w(float z) {
    float v = exp2_fast(fabsf(z) * -0.5770780163555852f);
    float w = 1.0f + v;
    float r = fmaf(w, -0.5f, 1.4571f);
    r = r * fmaf(-w, r, 2.0f);
    r = r * fmaf(-w, r, 2.0f);
    float s = v * r;
    float E = (z >= 0.0f) ? (-14.426950408889634f * s)
                          : fmaf(14.426950408889634f, s, -14.426950408889634f);
    return exp2_fast(E);
}

// ---------------- bn1 scale vector -------------------------------------------
__global__ void sc_kernel(const float* __restrict__ g, const float* __restrict__ ms,
                          float* __restrict__ sc)
{
    int i = blockIdx.x * blockDim.x + threadIdx.x;
    if (i < Cc) sc[i] = rsqrtf(ms[i] + EPSf) * g[i];
}

// ---------------- RoPE table --------------------------------------------------
__global__ void rope_tab_kernel(float* __restrict__ tab)
{
    int idx = blockIdx.x * blockDim.x + threadIdx.x;
    if (idx < Sq * 64) {
        int s = idx >> 6, f = idx & 63;
        float geom = expf(logf(1985.0f) * (float)f * (1.0f / 63.0f));
        float th = (float)s / ((float)f + geom);
        tab[idx * 2 + 0] = cosf(th);
        tab[idx * 2 + 1] = sinf(th);
    }
}

// ================= warp-MMA split-bf16 GEMM machinery =========================
#define APITCH 80
#define BPITCH 272

// ---------------- fused QKV projection (bn1 folded into A load) ---------------
// grid (23, 32): bx 0..15 -> Wq, 16..19 -> Wk, 20..22 -> Wv.
__global__ void __launch_bounds__(256)
gemm_qkv(const float* __restrict__ x, const float* __restrict__ sc,
         const float* __restrict__ Wq, const float* __restrict__ Wk,
         const float* __restrict__ Wv,
         float* __restrict__ qo, float* __restrict__ ko, float* __restrict__ vo)
{
    __shared__ __align__(16) uint8_t As_h[128 * APITCH];
    __shared__ __align__(16) uint8_t As_l[128 * APITCH];
    __shared__ __align__(16) uint8_t Bs_h[32 * BPITCH];
    __shared__ __align__(16) uint8_t Bs_l[32 * BPITCH];

    int t    = threadIdx.x;
    int wid  = t >> 5;
    int lane = t & 31;
    int bm   = blockIdx.y * 128;
    int bx   = blockIdx.x;

    const float* W; float* Cout; int Nloc, ncol;
    if (bx < 16)      { W = Wq; Cout = qo; Nloc = 2048; ncol = bx * 128; }
    else if (bx < 20) { W = Wk; Cout = ko; Nloc = 512;  ncol = (bx - 16) * 128; }
    else              { W = Wv; Cout = vo; Nloc = 384;  ncol = (bx - 20) * 128; }

    int wm = (wid & 1) * 64;
    int wn = (wid >> 1) * 32;

    float acc[4][4][4];
#pragma unroll
    for (int i = 0; i < 4; i++)
#pragma unroll
        for (int j = 0; j < 4; j++)
#pragma unroll
            for (int r = 0; r < 4; r++) acc[i][j][r] = 0.f;

    uint32_t ah_base = smem_u32(As_h), al_base = smem_u32(As_l);
    uint32_t bh_base = smem_u32(Bs_h), bl_base = smem_u32(Bs_l);

    int gg = lane >> 3, rr = lane & 7;
    uint32_t a_off = (uint32_t)(((gg & 1) * 8 + rr) * APITCH + (gg >> 1) * 16);
    uint32_t b_off = (uint32_t)(((gg & 1) * 8 + rr) * BPITCH + (gg >> 1) * 16);

    float4 aR[4], bR[4];
    auto loadA = [&](int kc) {
#pragma unroll
        for (int it = 0; it < 4; it++) {
            int idx = t + it * 256;
            int m = idx >> 3, kq = idx & 7;
            float4 a = *reinterpret_cast<const float4*>(x + (size_t)(bm + m) * Cc + kc + kq * 4);
            float4 s = *reinterpret_cast<const float4*>(sc + kc + kq * 4);
            a.x *= s.x; a.y *= s.y; a.z *= s.z; a.w *= s.w;
            aR[it] = a;
        }
    };
    auto loadB = [&](int kc) {
#pragma unroll
        for (int it = 0; it < 4; it++) {
            int idx = t + it * 256;
            int kk = idx >> 5, nq = idx & 31;
            bR[it] = *reinterpret_cast<const float4*>(W + (size_t)(kc + kk) * Nloc + ncol + nq * 4);
        }
    };
    auto stsAB = [&]() {
#pragma unroll
        for (int it = 0; it < 4; it++) {
            int idx = t + it * 256;
            int m = idx >> 3, kq = idx & 7;
            uint2 hi, lo;
            cvt_split4(aR[it], hi, lo);
            uint32_t off = (uint32_t)(m * APITCH + kq * 8);
            *reinterpret_cast<uint2*>(As_h + off) = hi;
            *reinterpret_cast<uint2*>(As_l + off) = lo;
        }
#pragma unroll
        for (int it = 0; it < 4; it++) {
            int idx = t + it * 256;
            int kk = idx >> 5, nq = idx & 31;
            uint2 hi, lo;
            cvt_split4(bR[it], hi, lo);
            uint32_t off = (uint32_t)(kk * BPITCH + nq * 8);
            *reinterpret_cast<uint2*>(Bs_h + off) = hi;
            *reinterpret_cast<uint2*>(Bs_l + off) = lo;
        }
    };

    const int NC = Cc / 32;     // 48
    loadA(0); loadB(0);
    for (int ic = 0; ic < NC; ic++) {
        stsAB();
        __syncthreads();
        if (ic + 1 < NC) { loadA((ic + 1) * 32); loadB((ic + 1) * 32); }

#pragma unroll
        for (int ks = 0; ks < 2; ks++) {
            uint32_t Bh[8], Bl[8];
            uint32_t bko = (uint32_t)(ks * 16 * BPITCH) + (uint32_t)(wn * 2);
            ldsm_x4t(&Bh[0], bh_base + b_off + bko);
            ldsm_x4t(&Bh[4], bh_base + b_off + bko + 32);
            ldsm_x4t(&Bl[0], bl_base + b_off + bko);
            ldsm_x4t(&Bl[4], bl_base + b_off + bko + 32);
#pragma unroll
            for (int mt = 0; mt < 4; mt++) {
                uint32_t Ah[4], Al[4];
                uint32_t aro = (uint32_t)((wm + mt * 16) * APITCH + ks * 32);
                ldsm_x4(Ah, ah_base + a_off + aro);
                ldsm_x4(Al, al_base + a_off + aro);
#pragma unroll
                for (int nt = 0; nt < 4; nt++) {
                    mma16816(acc[mt][nt], Ah, &Bh[nt * 2]);
                    mma16816(acc[mt][nt], Ah, &Bl[nt * 2]);
                    mma16816(acc[mt][nt], Al, &Bh[nt * 2]);
                }
            }
        }
        __syncthreads();
    }

#pragma unroll
    for (int mt = 0; mt < 4; mt++) {
#pragma unroll
        for (int nt = 0; nt < 4; nt++) {
            int lcol = wn + nt * 8 + (lane & 3) * 2;
            int row0 = bm + wm + mt * 16 + (lane >> 2);
            float2 o0, o1;
            o0.x = acc[mt][nt][0]; o0.y = acc[mt][nt][1];
            o1.x = acc[mt][nt][2]; o1.y = acc[mt][nt][3];
            *reinterpret_cast<float2*>(Cout + (size_t)row0 * Nloc + ncol + lcol) = o0;
            *reinterpret_cast<float2*>(Cout + (size_t)(row0 + 8) * Nloc + ncol + lcol) = o1;
        }
    }
}

// ---------------- O projection (+bias, *bn2) with pipeline --------------------
__global__ void __launch_bounds__(256)
gemm_mma(const float* __restrict__ A, const float* __restrict__ B,
         float* __restrict__ C, int M, int N, int K,
         const float* __restrict__ bias,
         const float* __restrict__ g2, const float* __restrict__ ms2)
{
    __shared__ __align__(16) uint8_t As_h[128 * APITCH];
    __shared__ __align__(16) uint8_t As_l[128 * APITCH];
    __shared__ __align__(16) uint8_t Bs_h[32 * BPITCH];
    __shared__ __align__(16) uint8_t Bs_l[32 * BPITCH];
    __shared__ float s_bias[128], s_scale[128];

    int t    = threadIdx.x;
    int wid  = t >> 5;
    int lane = t & 31;
    int bm   = blockIdx.y * 128;
    int bn   = blockIdx.x * 128;
    int wm   = (wid & 1) * 64;
    int wn   = (wid >> 1) * 32;

    if (t < 128) {
        s_bias[t]  = bias[bn + t];
        s_scale[t] = g2[bn + t] * rsqrtf(ms2[bn + t] + EPSf);
    }

    float acc[4][4][4];
#pragma unroll
    for (int i = 0; i < 4; i++)
#pragma unroll
        for (int j = 0; j < 4; j++)
#pragma unroll
            for (int r = 0; r < 4; r++) acc[i][j][r] = 0.f;

    uint32_t ah_base = smem_u32(As_h), al_base = smem_u32(As_l);
    uint32_t bh_base = smem_u32(Bs_h), bl_base = smem_u32(Bs_l);

    int gg = lane >> 3, rr = lane & 7;
    uint32_t a_off = (uint32_t)(((gg & 1) * 8 + rr) * APITCH + (gg >> 1) * 16);
    uint32_t b_off = (uint32_t)(((gg & 1) * 8 + rr) * BPITCH + (gg >> 1) * 16);

    float4 aR[4], bR[4];
    auto loadA = [&](int kc) {
#pragma unroll
        for (int it = 0; it < 4; it++) {
            int idx = t + it * 256;
            int m = idx >> 3, kq = idx & 7;
            aR[it] = *reinterpret_cast<const float4*>(A + (size_t)(bm + m) * K + kc + kq * 4);
        }
    };
    auto loadB = [&](int kc) {
#pragma unroll
        for (int it = 0; it < 4; it++) {
            int idx = t + it * 256;
            int kk = idx >> 5, nq = idx & 31;
            bR[it] = *reinterpret_cast<const float4*>(B + (size_t)(kc + kk) * N + bn + nq * 4);
        }
    };
    auto stsAB = [&]() {
#pragma unroll
        for (int it = 0; it < 4; it++) {
            int idx = t + it * 256;
            int m = idx >> 3, kq = idx & 7;
            uint2 hi, lo;
            cvt_split4(aR[it], hi, lo);
            uint32_t off = (uint32_t)(m * APITCH + kq * 8);
            *reinterpret_cast<uint2*>(As_h + off) = hi;
            *reinterpret_cast<uint2*>(As_l + off) = lo;
        }
#pragma unroll
        for (int it = 0; it < 4; it++) {
            int idx = t + it * 256;
            int kk = idx >> 5, nq = idx & 31;
            uint2 hi, lo;
            cvt_split4(bR[it], hi, lo);
            uint32_t off = (uint32_t)(kk * BPITCH + nq * 8);
            *reinterpret_cast<uint2*>(Bs_h + off) = hi;
            *reinterpret_cast<uint2*>(Bs_l + off) = lo;
        }
    };

    const int NC = K / 32;
    loadA(0); loadB(0);
    for (int ic = 0; ic < NC; ic++) {
        stsAB();
        __syncthreads();
        if (ic + 1 < NC) { loadA((ic + 1) * 32); loadB((ic + 1) * 32); }

#pragma unroll
        for (int ks = 0; ks < 2; ks++) {
            uint32_t Bh[8], Bl[8];
            uint32_t bko = (uint32_t)(ks * 16 * BPITCH) + (uint32_t)(wn * 2);
            ldsm_x4t(&Bh[0], bh_base + b_off + bko);
            ldsm_x4t(&Bh[4], bh_base + b_off + bko + 32);
            ldsm_x4t(&Bl[0], bl_base + b_off + bko);
            ldsm_x4t(&Bl[4], bl_base + b_off + bko + 32);
#pragma unroll
            for (int mt = 0; mt < 4; mt++) {
                uint32_t Ah[4], Al[4];
                uint32_t aro = (uint32_t)((wm + mt * 16) * APITCH + ks * 32);
                ldsm_x4(Ah, ah_base + a_off + aro);
                ldsm_x4(Al, al_base + a_off + aro);
#pragma unroll
                for (int nt = 0; nt < 4; nt++) {
                    mma16816(acc[mt][nt], Ah, &Bh[nt * 2]);
                    mma16816(acc[mt][nt], Ah, &Bl[nt * 2]);
                    mma16816(acc[mt][nt], Al, &Bh[nt * 2]);
                }
            }
        }
        __syncthreads();
    }

#pragma unroll
    for (int mt = 0; mt < 4; mt++) {
#pragma unroll
        for (int nt = 0; nt < 4; nt++) {
            int lcol = wn + nt * 8 + (lane & 3) * 2;
            int row0 = bm + wm + mt * 16 + (lane >> 2);
            float b0 = s_bias[lcol], b1 = s_bias[lcol + 1];
            float s0 = s_scale[lcol], s1 = s_scale[lcol + 1];
            float2 o0, o1;
            o0.x = (acc[mt][nt][0] + b0) * s0;
            o0.y = (acc[mt][nt][1] + b1) * s1;
            o1.x = (acc[mt][nt][2] + b0) * s0;
            o1.y = (acc[mt][nt][3] + b1) * s1;
            *reinterpret_cast<float2*>(C + (size_t)row0 * N + bn + lcol) = o0;
            *reinterpret_cast<float2*>(C + (size_t)(row0 + 8) * N + bn + lcol) = o1;
        }
    }
}

// ---------------- layernorm(128) + RoPE for q/k (in place) -------------------
__global__ void __launch_bounds__(128)
ln_rope_kernel(float* __restrict__ qk, const float* __restrict__ g,
               const float* __restrict__ b, const float* __restrict__ tab, int H)
{
    int row = blockIdx.x;
    int tid = threadIdx.x;
    int s   = (row / H) % Sq;

    float* p = qk + (size_t)row * DQK;
    float v = p[tid];

    __shared__ float red[4], red2[4];
    float sum = v;
#pragma unroll
    for (int o = 16; o > 0; o >>= 1) sum += __shfl_xor_sync(0xffffffffu, sum, o);
    if ((tid & 31) == 0) red[tid >> 5] = sum;
    __syncthreads();
    float mu = (red[0] + red[1] + red[2] + red[3]) * (1.0f / DQK);

    float d = v - mu;
    float sq = d * d;
#pragma unroll
    for (int o = 16; o > 0; o >>= 1) sq += __shfl_xor_sync(0xffffffffu, sq, o);
    if ((tid & 31) == 0) red2[tid >> 5] = sq;
    __syncthreads();
    float var = (red2[0] + red2[1] + red2[2] + red2[3]) * (1.0f / DQK);

    float norm = d * rsqrtf(var + EPSf) * g[tid] + b[tid];

    float2 cs2 = *reinterpret_cast<const float2*>(tab + ((size_t)s * 64 + (tid >> 1)) * 2);
    float partner = __shfl_xor_sync(0xffffffffu, norm, 1);
    float rot = (tid & 1) ? partner : -partner;
    p[tid] = norm * cs2.x + rot * cs2.y;
}

// ---------------- layernorm(96) for v (in place) -----------------------------
__global__ void __launch_bounds__(96)
ln_v_kernel(float* __restrict__ vv, const float* __restrict__ g, const float* __restrict__ b)
{
    int row = blockIdx.x;
    int tid = threadIdx.x;
    float* p = vv + (size_t)row * DV;
    float v = p[tid];

    __shared__ float red[3], red2[3];
    float sum = v;
#pragma unroll
    for (int o = 16; o > 0; o >>= 1) sum += __shfl_xor_sync(0xffffffffu, sum, o);
    if ((tid & 31) == 0) red[tid >> 5] = sum;
    __syncthreads();
    float mu = (red[0] + red[1] + red[2]) * (1.0f / DV);

    float d = v - mu;
    float sq = d * d;
#pragma unroll
    for (int o = 16; o > 0; o >>= 1) sq += __shfl_xor_sync(0xffffffffu, sq, o);
    if ((tid & 31) == 0) red2[tid >> 5] = sq;
    __syncthreads();
    float var = (red2[0] + red2[1] + red2[2]) * (1.0f / DV);

    p[tid] = d * rsqrtf(var + EPSf) * g[tid] + b[tid];
}

// ================= tensor-core flash attention (K/V prefetch pipeline) ========
#define KT 64
#define QPITCH 272
#define KPITCH 272
#define VPITCH 208
#define SM_QH 0
#define SM_QL 34816
#define SM_KH 69632
#define SM_KL (SM_KH + 17408)
#define SM_VH (SM_KL + 17408)
#define SM_VL (SM_VH + 13312)
#define ATT_SMEM (SM_VL + 13312)    // 131072

__global__ void __launch_bounds__(256, 1)
attn_mma(const float* __restrict__ Q, const float* __restrict__ K,
         const float* __restrict__ V, float* __restrict__ Y)
{
    extern __shared__ __align__(16) uint8_t sm[];
    uint8_t* Qh = sm + SM_QH;  uint8_t* Ql = sm + SM_QL;
    uint8_t* Kh = sm + SM_KH;  uint8_t* Kl = sm + SM_KL;
    uint8_t* Vh = sm + SM_VH;  uint8_t* Vl = sm + SM_VL;

    int t = threadIdx.x, wid = t >> 5, lane = t & 31;
    int qt = blockIdx.x, h = blockIdx.y, b = blockIdx.z;
    int kvh = h & (HKVn - 1);
    int q0  = qt * 128;

    // ---- load Q tile (scaled by 1/sqrt(128) BEFORE split), hi/lo bf16 -------
    const float qsc = 0.08838834764831845f;
    const float* Qg = Q + ((size_t)(b * Sq + q0) * HQn + h) * DQK;
#pragma unroll
    for (int it = 0; it < 16; it++) {
        int idx = t + it * 256;
        int m = idx >> 5, dq = idx & 31;
        float4 a = *reinterpret_cast<const float4*>(Qg + (size_t)m * (HQn * DQK) + dq * 4);
        a.x *= qsc; a.y *= qsc; a.z *= qsc; a.w *= qsc;
        uint2 hi, lo;
        cvt_split4(a, hi, lo);
        uint32_t off = (uint32_t)(m * QPITCH + dq * 8);
        *reinterpret_cast<uint2*>(Qh + off) = hi;
        *reinterpret_cast<uint2*>(Ql + off) = lo;
    }

    uint32_t qh_b = smem_u32(Qh), ql_b = smem_u32(Ql);
    uint32_t kh_b = smem_u32(Kh), kl_b = smem_u32(Kl);
    uint32_t vh_b = smem_u32(Vh), vl_b = smem_u32(Vl);

    int g = lane >> 3, r = lane & 7;
    uint32_t qk_off = (uint32_t)(((g & 1) * 8 + r) * QPITCH + (g >> 1) * 16);
    uint32_t v_off  = (uint32_t)(((g & 1) * 8 + r) * VPITCH + (g >> 1) * 16);
    uint32_t qrow_off = (uint32_t)(wid * 16 * QPITCH);

    const float* Kg0 = K + ((size_t)b * Sq * HKVn + kvh) * DQK;
    const float* Vg0 = V + ((size_t)b * Sq * HKVn + kvh) * DV;

    float4 kreg[8], vreg[6];
    auto loadK = [&](int kt0) {
        const float* Kg = Kg0 + (size_t)kt0 * HKVn * DQK;
#pragma unroll
        for (int it = 0; it < 8; it++) {
            int idx = t + it * 256;
            int m = idx >> 5, dq = idx & 31;
            kreg[it] = *reinterpret_cast<const float4*>(Kg + (size_t)m * (HKVn * DQK) + dq * 4);
        }
    };
    auto loadV = [&](int kt0) {
        const float* Vg = Vg0 + (size_t)kt0 * HKVn * DV;
#pragma unroll
        for (int it = 0; it < 6; it++) {
            int idx = t + it * 256;
            int m = idx / 24, c = idx - m * 24;
            vreg[it] = *reinterpret_cast<const float4*>(Vg + (size_t)m * (HKVn * DV) + c * 4);
        }
    };
    auto stsKV = [&]() {
#pragma unroll
        for (int it = 0; it < 8; it++) {
            int idx = t + it * 256;
            int m = idx >> 5, dq = idx & 31;
            uint2 hi, lo;
            cvt_split4(kreg[it], hi, lo);
            uint32_t off = (uint32_t)(m * KPITCH + dq * 8);
            *reinterpret_cast<uint2*>(Kh + off) = hi;
            *reinterpret_cast<uint2*>(Kl + off) = lo;
        }
#pragma unroll
        for (int it = 0; it < 6; it++) {
            int idx = t + it * 256;
            int m = idx / 24, c = idx - m * 24;
            uint2 hi, lo;
            cvt_split4(vreg[it], hi, lo);
            uint32_t off = (uint32_t)(m * VPITCH + c * 8);
            *reinterpret_cast<uint2*>(Vh + off) = hi;
            *reinterpret_cast<uint2*>(Vl + off) = lo;
        }
    };

    float yacc[12][4];
#pragma unroll
    for (int i = 0; i < 12; i++)
#pragma unroll
        for (int j = 0; j < 4; j++) yacc[i][j] = 0.f;
    float lsum0 = 0.f, lsum1 = 0.f;

    loadK(0); loadV(0);
    for (int kt0 = 0; kt0 < Sq; kt0 += KT) {
        stsKV();
        __syncthreads();
        if (kt0 + KT < Sq) { loadK(kt0 + KT); loadV(kt0 + KT); }

        // ---- QK: S[8 n-tiles][4] over d=128 ---------------------------------
        float S[8][4];
#pragma unroll
        for (int i = 0; i < 8; i++)
#pragma unroll
            for (int j = 0; j < 4; j++) S[i][j] = 0.f;

#pragma unroll
        for (int kt16 = 0; kt16 < 8; kt16++) {
            uint32_t aQh[4], aQl[4];
            uint32_t qa = qk_off + qrow_off + (uint32_t)(kt16 * 32);
            ldsm_x4(aQh, qh_b + qa);
            ldsm_x4(aQl, ql_b + qa);
#pragma unroll
            for (int nt2 = 0; nt2 < 4; nt2++) {
                uint32_t bKh[4], bKl[4];
                uint32_t ka = qk_off + (uint32_t)(nt2 * 16 * KPITCH + kt16 * 32);
                ldsm_x4(bKh, kh_b + ka);
                ldsm_x4(bKl, kl_b + ka);
                mma_ab(S[2*nt2+0], aQh, bKh[0], bKh[2]);
                mma_ab(S[2*nt2+0], aQh, bKl[0], bKl[2]);
                mma_ab(S[2*nt2+0], aQl, bKh[0], bKh[2]);
                mma_ab(S[2*nt2+1], aQh, bKh[1], bKh[3]);
                mma_ab(S[2*nt2+1], aQh, bKl[1], bKl[3]);
                mma_ab(S[2*nt2+1], aQl, bKh[1], bKh[3]);
            }
        }

        // ---- softcap + exp (MUFU-free), accumulate row sums -----------------
#pragma unroll
        for (int nt = 0; nt < 8; nt++) {
            float f0 = softcap_w(S[nt][0]);
            float f1 = softcap_w(S[nt][1]);
            float f2 = softcap_w(S[nt][2]);
            float f3 = softcap_w(S[nt][3]);
            S[nt][0] = f0; S[nt][1] = f1; S[nt][2] = f2; S[nt][3] = f3;
            lsum0 += f0 + f1;
            lsum1 += f2 + f3;
        }

        // ---- PV: Y += P @ V --------------------------------------------------
#pragma unroll
        for (int kt16 = 0; kt16 < 4; kt16++) {
            uint32_t aPh[4], aPl[4];
            {
                float* c0 = S[2*kt16];
                float* c1 = S[2*kt16+1];
                aPh[0] = pack_bf16(c0[0], c0[1]);
                aPh[1] = pack_bf16(c0[2], c0[3]);
                aPh[2] = pack_bf16(c1[0], c1[1]);
                aPh[3] = pack_bf16(c1[2], c1[3]);
                __nv_bfloat162* p0 = reinterpret_cast<__nv_bfloat162*>(&aPh[0]);
                __nv_bfloat162* p1 = reinterpret_cast<__nv_bfloat162*>(&aPh[1]);
                __nv_bfloat162* p2 = reinterpret_cast<__nv_bfloat162*>(&aPh[2]);
                __nv_bfloat162* p3 = reinterpret_cast<__nv_bfloat162*>(&aPh[3]);
                aPl[0] = pack_bf16(c0[0] - __bfloat162float(p0->x), c0[1] - __bfloat162float(p0->y));
                aPl[1] = pack_bf16(c0[2] - __bfloat162float(p1->x), c0[3] - __bfloat162float(p1->y));
                aPl[2] = pack_bf16(c1[0] - __bfloat162float(p2->x), c1[1] - __bfloat162float(p2->y));
                aPl[3] = pack_bf16(c1[2] - __bfloat162float(p3->x), c1[3] - __bfloat162float(p3->y));
            }
#pragma unroll
            for (int nv2 = 0; nv2 < 6; nv2++) {
                uint32_t bVh[4], bVl[4];
                uint32_t va = v_off + (uint32_t)(kt16 * 16 * VPITCH + nv2 * 32);
                ldsm_x4t(bVh, vh_b + va);
                ldsm_x4t(bVl, vl_b + va);
                mma_ab(yacc[2*nv2+0], aPh, bVh[0], bVh[1]);
                mma_ab(yacc[2*nv2+0], aPh, bVl[0], bVl[1]);
                mma_ab(yacc[2*nv2+0], aPl, bVh[0], bVh[1]);
                mma_ab(yacc[2*nv2+1], aPh, bVh[2], bVh[3]);
                mma_ab(yacc[2*nv2+1], aPh, bVl[2], bVl[3]);
                mma_ab(yacc[2*nv2+1], aPl, bVh[2], bVh[3]);
            }
        }
        __syncthreads();
    }

    // ---- normalize + store ---------------------------------------------------
    lsum0 += __shfl_xor_sync(0xffffffffu, lsum0, 1);
    lsum0 += __shfl_xor_sync(0xffffffffu, lsum0, 2);
    lsum1 += __shfl_xor_sync(0xffffffffu, lsum1, 1);
    lsum1 += __shfl_xor_sync(0xffffffffu, lsum1, 2);
    float inv0 = 1.0f / lsum0;
    float inv1 = 1.0f / lsum1;

    int row0 = q0 + wid * 16 + (lane >> 2);
    float* Y0 = Y + ((size_t)(b * Sq + row0) * HQn + h) * DV;
    float* Y1 = Y + ((size_t)(b * Sq + row0 + 8) * HQn + h) * DV;
    int cbase = (lane & 3) * 2;
#pragma unroll
    for (int nt = 0; nt < 12; nt++) {
        float2 o0, o1;
        o0.x = yacc[nt][0] * inv0; o0.y = yacc[nt][1] * inv0;
        o1.x = yacc[nt][2] * inv1; o1.y = yacc[nt][3] * inv1;
        *reinterpret_cast<float2*>(Y0 + nt * 8 + cbase) = o0;
        *reinterpret_cast<float2*>(Y1 + nt * 8 + cbase) = o1;
    }
}

// ---------------- host launcher ----------------------------------------------
extern "C" void kernel_launch(void* const* d_in, const int* in_sizes, int n_in,
                              void* d_out, int out_size)
{
    const float* x      = (const float*)d_in[0];
    const float* bn1_g  = (const float*)d_in[1];
    const float* bn1_ms = (const float*)d_in[2];
    const float* Wq     = (const float*)d_in[3];
    const float* Wk     = (const float*)d_in[4];
    const float* Wv     = (const float*)d_in[5];
    const float* qn_g   = (const float*)d_in[6];
    const float* qn_b   = (const float*)d_in[7];
    const float* kn_g   = (const float*)d_in[8];
    const float* kn_b   = (const float*)d_in[9];
    const float* vn_g   = (const float*)d_in[10];
    const float* vn_b   = (const float*)d_in[11];
    const float* Wo     = (const float*)d_in[12];
    const float* bo     = (const float*)d_in[13];
    const float* bn2_g  = (const float*)d_in[14];
    const float* bn2_ms = (const float*)d_in[15];
    float* out = (float*)d_out;

    static float *pq = nullptr, *pk = nullptr, *pv = nullptr,
                 *py = nullptr, *prope = nullptr, *psc = nullptr;
    if (!pq) {
        cudaGetSymbolAddress((void**)&pq, g_q);
        cudaGetSymbolAddress((void**)&pk, g_k);
        cudaGetSymbolAddress((void**)&pv, g_v);
        cudaGetSymbolAddress((void**)&py, g_y);
        cudaGetSymbolAddress((void**)&prope, g_rope);
        cudaGetSymbolAddress((void**)&psc, g_sc);
        cudaFuncSetAttribute(attn_mma, cudaFuncAttributeMaxDynamicSharedMemorySize,
                             ATT_SMEM);
    }

    const int M = Bq * Sq;  // 4096

    sc_kernel<<<(Cc + 255) / 256, 256>>>(bn1_g, bn1_ms, psc);
    rope_tab_kernel<<<(Sq * 64 + 255) / 256, 256>>>(prope);

    gemm_qkv<<<dim3(23, M / 128), 256>>>(x, psc, Wq, Wk, Wv, pq, pk, pv);

    ln_rope_kernel<<<M * HQn, 128>>>(pq, qn_g, qn_b, prope, HQn);
    ln_rope_kernel<<<M * HKVn, 128>>>(pk, kn_g, kn_b, prope, HKVn);
    ln_v_kernel<<<M * HKVn, 96>>>(pv, vn_g, vn_b);

    attn_mma<<<dim3(Sq / 128, HQn, Bq), 256, ATT_SMEM>>>(pq, pk, pv, py);

    gemm_mma<<<dim3(Cc / 128, M / 128), 256>>>(
        py, Wo, out, M, Cc, Cc, bo, bn2_g, bn2_ms);
}